// round 14
// baseline (speedup 1.0000x reference)
#include <cuda_runtime.h>
#include <cuda_fp16.h>
#include <cstdint>
#include <math.h>

#define Bsz 2
#define Tt 2048
#define Dd 2048
#define Hh 16
#define KVh 4
#define HD 128
#define GQ (Hh/KVh)
#define NQKV 3072

// ---------------- scratch ----------------
__device__ __half g_xs_h[(size_t)Bsz*Tt*Dd];
__device__ __half g_xs_l[(size_t)Bsz*Tt*Dd];
__device__ __half g_os_h[(size_t)Bsz*Tt*Dd];
__device__ __half g_os_l[(size_t)Bsz*Tt*Dd];
__device__ __half g_wqkvt_h[(size_t)NQKV*Dd];
__device__ __half g_wot_h[(size_t)Dd*Dd];

__device__ __half g_qh[(size_t)Bsz*Hh*Tt*HD];
__device__ __half g_ql[(size_t)Bsz*Hh*Tt*HD];
__device__ __half g_kh[(size_t)Bsz*KVh*Tt*HD];
__device__ __half g_vh[(size_t)Bsz*KVh*Tt*HD];

__device__ float2 g_rope[(size_t)Tt*64];

// ---------------- helpers ----------------
__device__ __forceinline__ uint32_t smem_u32(const void* p) {
    uint32_t a;
    asm("{ .reg .u64 t; cvta.to.shared.u64 t, %1; cvt.u32.u64 %0, t; }" : "=r"(a) : "l"(p));
    return a;
}

#define CP_ASYNC16(dst, src) \
    asm volatile("cp.async.cg.shared.global [%0], [%1], 16;" :: "r"(dst), "l"(src))
#define CP_COMMIT() asm volatile("cp.async.commit_group;")
#define CP_WAIT0()  asm volatile("cp.async.wait_group 0;")
#define CP_WAIT1()  asm volatile("cp.async.wait_group 1;")

#define LDSM_X4(r0, r1, r2, r3, addr) \
    asm volatile("ldmatrix.sync.aligned.m8n8.x4.shared.b16 {%0,%1,%2,%3}, [%4];" \
        : "=r"(r0), "=r"(r1), "=r"(r2), "=r"(r3) : "r"(addr))

#define LDSM_X4T(r0, r1, r2, r3, addr) \
    asm volatile("ldmatrix.sync.aligned.m8n8.x4.trans.shared.b16 {%0,%1,%2,%3}, [%4];" \
        : "=r"(r0), "=r"(r1), "=r"(r2), "=r"(r3) : "r"(addr))

#define MMA16816(c, a, b0, b1) \
    asm volatile("mma.sync.aligned.m16n8k16.row.col.f32.f16.f16.f32 " \
        "{%0,%1,%2,%3},{%4,%5,%6,%7},{%8,%9},{%0,%1,%2,%3};" \
        : "+f"((c)[0]), "+f"((c)[1]), "+f"((c)[2]), "+f"((c)[3]) \
        : "r"((a)[0]), "r"((a)[1]), "r"((a)[2]), "r"((a)[3]), "r"(b0), "r"(b1))

__device__ __forceinline__ uint32_t packh2(__half lo, __half hi) {
    union { __half2 v; uint32_t u; } cv;
    cv.v = __halves2half2(lo, hi);
    return cv.u;
}

// ---------------- conversion kernels ----------------
__global__ void split_kernel(const float* __restrict__ A,
                             __half* __restrict__ H,
                             __half* __restrict__ L, int n4)
{
    int i = blockIdx.x * blockDim.x + threadIdx.x;
    int stride = gridDim.x * blockDim.x;
    for (; i < n4; i += stride) {
        float4 a = ((const float4*)A)[i];
        __half h0 = __float2half_rn(a.x);
        __half h1 = __float2half_rn(a.y);
        __half h2 = __float2half_rn(a.z);
        __half h3 = __float2half_rn(a.w);
        __half l0 = __float2half_rn(a.x - __half2float(h0));
        __half l1 = __float2half_rn(a.y - __half2float(h1));
        __half l2 = __float2half_rn(a.z - __half2float(h2));
        __half l3 = __float2half_rn(a.w - __half2float(h3));
        ((__half2*)H)[2*i]   = __halves2half2(h0, h1);
        ((__half2*)H)[2*i+1] = __halves2half2(h2, h3);
        ((__half2*)L)[2*i]   = __halves2half2(l0, l1);
        ((__half2*)L)[2*i+1] = __halves2half2(l2, l3);
    }
}

__global__ void tsplit_all_kernel(
    const float* __restrict__ Wq, const float* __restrict__ Wk,
    const float* __restrict__ Wv, const float* __restrict__ Wo,
    __half* __restrict__ QKVh, __half* __restrict__ Oh)
{
    __shared__ float t[32][33];
    int z = blockIdx.z;
    const float* W;
    __half* Th;
    int N;
    if (z == 0)      { W = Wq; Th = QKVh;                      N = 2048; }
    else if (z == 1) { W = Wk; Th = QKVh + (size_t)2048 * Dd;  N = 512; }
    else if (z == 2) { W = Wv; Th = QKVh + (size_t)2560 * Dd;  N = 512; }
    else             { W = Wo; Th = Oh;                        N = 2048; }
    int n0 = blockIdx.x * 32, k0 = blockIdx.y * 32;
    if (n0 >= N) return;
    const int K = Dd;
    int tx = threadIdx.x, ty0 = threadIdx.y;
#pragma unroll
    for (int j = 0; j < 4; j++) {
        int ty = ty0 + j * 8;
        t[ty][tx] = W[(size_t)(k0 + ty) * N + n0 + tx];
    }
    __syncthreads();
#pragma unroll
    for (int j = 0; j < 4; j++) {
        int ty = ty0 + j * 8;
        Th[(size_t)(n0 + ty) * K + k0 + tx] = __float2half_rn(t[tx][ty]);
    }
}

__global__ void rope_table_kernel(float2* __restrict__ tab)
{
    int i = blockIdx.x * blockDim.x + threadIdx.x;
    int f = i & 63;
    int t = i >> 6;
    float inv = powf(10000.0f, -(float)f * (1.0f / 64.0f));
    float s, c;
    sincosf((float)t * inv, &s, &c);
    tab[i] = make_float2(s, c);
}

// ---------------- fp16 2-term GEMM: 128x128 CTA, 128 thr, warp tile 64x64 ----------------
#define KSP 40
#define TILE_B (128 * KSP * 2)        // 10240
#define STAGE_B (3 * TILE_B)          // 30720 (Ah, Al, Bh)
#define GEMM_SMEM (2 * STAGE_B)       // 61440

__global__ void __launch_bounds__(128, 2) mma_gemm(
    const __half* __restrict__ Ah, const __half* __restrict__ Al,
    const __half* __restrict__ Bh,
    float* __restrict__ C, int M, int N, int K, int mode,
    const float2* __restrict__ rope,
    __half* __restrict__ QH, __half* __restrict__ QL,
    __half* __restrict__ KH, __half* __restrict__ VH)
{
    extern __shared__ char sm[];
    uint32_t smem_base = smem_u32(sm);
    int tid = threadIdx.x;
    int wid = tid >> 5, lane = tid & 31;
    int wm = wid >> 1, wn = wid & 1;    // 2x2 grid, warp tile 64x64

    int m0 = blockIdx.y * 128, n0 = blockIdx.x * 128;
    int nstage = K / 32;

    float acc[4][8][4];
#pragma unroll
    for (int a = 0; a < 4; a++)
#pragma unroll
        for (int b = 0; b < 8; b++)
#pragma unroll
            for (int c = 0; c < 4; c++) acc[a][b][c] = 0.f;

    // one stage: 3 tiles x 512 chunks = 1536, 12 per thread (128 thr)
    auto load_stage = [&](int kc, int s) {
        int kcol = kc * 32;
        uint32_t sb = smem_base + s * STAGE_B;
#pragma unroll
        for (int i = 0; i < 12; i++) {
            int c = tid + i * 128;
            int tile = c >> 9;           // 0=Ah 1=Al 2=Bh
            int cid = c & 511;
            int row = cid >> 2, kch = cid & 3;
            const __half* src;
            if (tile == 0)      src = Ah + (size_t)(m0 + row) * K + kcol + kch * 8;
            else if (tile == 1) src = Al + (size_t)(m0 + row) * K + kcol + kch * 8;
            else                src = Bh + (size_t)(n0 + row) * K + kcol + kch * 8;
            uint32_t dst = sb + tile * TILE_B + (row * KSP + kch * 8) * 2;
            CP_ASYNC16(dst, src);
        }
    };

    load_stage(0, 0); CP_COMMIT();

    uint32_t aoff = ((wm * 64 + (lane & 15)) * KSP + ((lane >> 4) << 3)) * 2;
    uint32_t boff = ((wn * 64 + ((lane >> 4) << 3) + (lane & 7)) * KSP + (((lane >> 3) & 1) << 3)) * 2;

    for (int kc = 0; kc < nstage; kc++) {
        CP_WAIT0();
        __syncthreads();
        if (kc + 1 < nstage) { load_stage(kc + 1, (kc + 1) & 1); CP_COMMIT(); }

        uint32_t sb = smem_base + (kc & 1) * STAGE_B;
        uint32_t aHi = sb + aoff;
        uint32_t bHi = sb + 2 * TILE_B + boff;

#pragma unroll
        for (int kk = 0; kk < 2; kk++) {
            uint32_t ko = kk * 32;
            uint32_t bh[4][4];
#pragma unroll
            for (int pr = 0; pr < 4; pr++)
                LDSM_X4(bh[pr][0], bh[pr][1], bh[pr][2], bh[pr][3], bHi + pr * 16 * KSP * 2 + ko);
#pragma unroll
            for (int mt = 0; mt < 4; mt++) {
                uint32_t ah4[4], al4[4];
                LDSM_X4(ah4[0], ah4[1], ah4[2], ah4[3], aHi + mt * 16 * KSP * 2 + ko);
                LDSM_X4(al4[0], al4[1], al4[2], al4[3], aHi + TILE_B + mt * 16 * KSP * 2 + ko);
#pragma unroll
                for (int nt = 0; nt < 8; nt++) {
                    int pr = nt >> 1, ix = (nt & 1) * 2;
                    MMA16816(acc[mt][nt], ah4, bh[pr][ix], bh[pr][ix + 1]);
                }
#pragma unroll
                for (int nt = 0; nt < 8; nt++) {
                    int pr = nt >> 1, ix = (nt & 1) * 2;
                    MMA16816(acc[mt][nt], al4, bh[pr][ix], bh[pr][ix + 1]);
                }
            }
        }
    }

    if (mode == 0) {
#pragma unroll
        for (int mt = 0; mt < 4; mt++)
#pragma unroll
            for (int nt = 0; nt < 8; nt++) {
                int row = m0 + wm * 64 + mt * 16 + (lane >> 2);
                int col = n0 + wn * 64 + nt * 8 + (lane & 3) * 2;
                *(float2*)&C[(size_t)row * N + col]       = make_float2(acc[mt][nt][0], acc[mt][nt][1]);
                *(float2*)&C[(size_t)(row + 8) * N + col] = make_float2(acc[mt][nt][2], acc[mt][nt][3]);
            }
    } else {
        const float qscale = 0.08838834764831845f;
#pragma unroll
        for (int mt = 0; mt < 4; mt++)
#pragma unroll
            for (int nt = 0; nt < 8; nt++) {
                int colp = n0 + wn * 64 + nt * 8 + (lane & 3) * 2;
#pragma unroll
                for (int rr = 0; rr < 2; rr++) {
                    int row = m0 + wm * 64 + mt * 16 + (lane >> 2) + rr * 8;
                    float x1 = acc[mt][nt][rr * 2];
                    float x2 = acc[mt][nt][rr * 2 + 1];
                    int t = row & (Tt - 1);
                    int b = row >> 11;
                    if (colp < 2048) {
                        int hh = colp >> 7, d = colp & 127, f = d >> 1;
                        float2 sc2 = rope[t * 64 + f];
                        float v1 = (x1 * sc2.y - x2 * sc2.x) * qscale;
                        float v2 = (x1 * sc2.x + x2 * sc2.y) * qscale;
                        size_t o = ((size_t)(b * Hh + hh) * Tt + t) * HD;
                        __half h1 = __float2half_rn(v1);
                        __half h2 = __float2half_rn(v2);
                        QH[o + f]      = h1;
                        QL[o + f]      = __float2half_rn(v1 - __half2float(h1));
                        QH[o + 64 + f] = h2;
                        QL[o + 64 + f] = __float2half_rn(v2 - __half2float(h2));
                    } else if (colp < 2560) {
                        int kvh = (colp - 2048) >> 7, d = (colp - 2048) & 127, f = d >> 1;
                        float2 sc2 = rope[t * 64 + f];
                        float v1 = x1 * sc2.y - x2 * sc2.x;
                        float v2 = x1 * sc2.x + x2 * sc2.y;
                        size_t o = ((size_t)(b * KVh + kvh) * Tt + t) * HD;
                        KH[o + f]      = __float2half_rn(v1);
                        KH[o + 64 + f] = __float2half_rn(v2);
                    } else {
                        int kvh = (colp - 2560) >> 7, d = (colp - 2560) & 127;
                        size_t o = ((size_t)(b * KVh + kvh) * Tt + t) * HD + d;
                        *(__half2*)&VH[o] = __halves2half2(__float2half_rn(x1), __float2half_rn(x2));
                    }
                }
            }
    }
}

// ---------------- Flash attention fp16 2-term: Bq=64, 3 CTAs/SM (unchanged) ----------------
#define FSTR 136
#define FTB  (64 * FSTR * 2)          // 17408 per tile
#define FLASH_SMEM (4 * FTB)          // 69632

__global__ void __launch_bounds__(128, 3) flash_mma(
    const __half* __restrict__ Qh, const __half* __restrict__ Ql,
    const __half* __restrict__ Kh, const __half* __restrict__ Vh,
    __half* __restrict__ Oh, __half* __restrict__ Ol)
{
    extern __shared__ char sm[];
    uint32_t sb = smem_u32(sm);
    int tid = threadIdx.x, lane = tid & 31, wm = tid >> 5;
    int qt = gridDim.x - 1 - blockIdx.x;
    int h = blockIdx.y, b = blockIdx.z;
    int q0 = qt * 64;
    int kvh = h / GQ;

    const __half* Qhp = Qh + ((size_t)(b * Hh + h) * Tt + q0) * HD;
    const __half* Qlp = Ql + ((size_t)(b * Hh + h) * Tt + q0) * HD;
    const __half* Khp = Kh + (size_t)(b * KVh + kvh) * Tt * HD;
    const __half* Vhp = Vh + (size_t)(b * KVh + kvh) * Tt * HD;

#pragma unroll
    for (int i = 0; i < 8; i++) {
        int ch = tid + i * 128;
        int r = ch >> 4, c = ch & 15;
        uint32_t off = (uint32_t)(r * FSTR + c * 8) * 2;
        CP_ASYNC16(sb + off,       Qhp + (size_t)r * HD + c * 8);
        CP_ASYNC16(sb + FTB + off, Qlp + (size_t)r * HD + c * 8);
    }
    CP_COMMIT();

    float oc[16][4];
#pragma unroll
    for (int i = 0; i < 16; i++)
#pragma unroll
        for (int e = 0; e < 4; e++) oc[i][e] = 0.f;
    float mrow[2] = { -1e30f, -1e30f };
    float lrow[2] = { 0.f, 0.f };

    uint32_t q_add = (uint32_t)((wm * 16 + (lane & 15)) * FSTR + ((lane >> 4) << 3)) * 2;
    uint32_t k_add = (uint32_t)(((lane >> 4) * 8 + (lane & 7)) * FSTR + (((lane >> 3) & 1) << 3)) * 2;
    int vg = lane >> 3, vl8 = lane & 7;
    uint32_t v_add = (uint32_t)(((vg & 1) * 8 + vl8) * FSTR + ((vg >> 1) << 3)) * 2;

    int ntile = qt + 1;
    for (int j = 0; j < ntile; j++) {
        __syncthreads();
        const __half* kh = Khp + (size_t)j * 64 * HD;
        const __half* vh = Vhp + (size_t)j * 64 * HD;
#pragma unroll
        for (int i = 0; i < 8; i++) {
            int ch = tid + i * 128;
            int r = ch >> 4, c = ch & 15;
            uint32_t off = (uint32_t)(r * FSTR + c * 8) * 2;
            CP_ASYNC16(sb + 2 * FTB + off, kh + (size_t)r * HD + c * 8);
        }
        CP_COMMIT();
#pragma unroll
        for (int i = 0; i < 8; i++) {
            int ch = tid + i * 128;
            int r = ch >> 4, c = ch & 15;
            uint32_t off = (uint32_t)(r * FSTR + c * 8) * 2;
            CP_ASYNC16(sb + 3 * FTB + off, vh + (size_t)r * HD + c * 8);
        }
        CP_COMMIT();

        CP_WAIT1();
        __syncthreads();

        float sc[8][4];
#pragma unroll
        for (int nt = 0; nt < 8; nt++)
#pragma unroll
            for (int e = 0; e < 4; e++) sc[nt][e] = 0.f;

#pragma unroll
        for (int kb = 0; kb < 8; kb++) {
            uint32_t qh4[4], ql4[4];
            uint32_t ko = kb * 32;
            LDSM_X4(qh4[0], qh4[1], qh4[2], qh4[3], sb + q_add + ko);
            LDSM_X4(ql4[0], ql4[1], ql4[2], ql4[3], sb + FTB + q_add + ko);
            uint32_t kh4[4][4];
#pragma unroll
            for (int pr = 0; pr < 4; pr++) {
                uint32_t ra = pr * 16 * FSTR * 2 + ko;
                LDSM_X4(kh4[pr][0], kh4[pr][1], kh4[pr][2], kh4[pr][3], sb + 2 * FTB + k_add + ra);
            }
#pragma unroll
            for (int nt = 0; nt < 8; nt++) {
                int pr = nt >> 1, ix = (nt & 1) * 2;
                MMA16816(sc[nt], qh4, kh4[pr][ix], kh4[pr][ix + 1]);
            }
#pragma unroll
            for (int nt = 0; nt < 8; nt++) {
                int pr = nt >> 1, ix = (nt & 1) * 2;
                MMA16816(sc[nt], ql4, kh4[pr][ix], kh4[pr][ix + 1]);
            }
        }

        if (j == ntile - 1) {
            int row0 = q0 + wm * 16 + (lane >> 2);
#pragma unroll
            for (int nt = 0; nt < 8; nt++) {
                int col = j * 64 + nt * 8 + (lane & 3) * 2;
#pragma unroll
                for (int e = 0; e < 4; e++) {
                    int cc = col + (e & 1);
                    int rr = row0 + ((e >> 1) << 3);
                    if (cc > rr) sc[nt][e] = -1e30f;
                }
            }
        }

#pragma unroll
        for (int half = 0; half < 2; half++) {
            int e0 = half * 2;
            float mx = -1e30f;
#pragma unroll
            for (int nt = 0; nt < 8; nt++)
                mx = fmaxf(mx, fmaxf(sc[nt][e0], sc[nt][e0 + 1]));
            mx = fmaxf(mx, __shfl_xor_sync(0xffffffff, mx, 1));
            mx = fmaxf(mx, __shfl_xor_sync(0xffffffff, mx, 2));
            float mnew = fmaxf(mrow[half], mx);
            float alpha = __expf(mrow[half] - mnew);
            float sum = 0.f;
#pragma unroll
            for (int nt = 0; nt < 8; nt++) {
                float p0 = __expf(sc[nt][e0]     - mnew);
                float p1 = __expf(sc[nt][e0 + 1] - mnew);
                sc[nt][e0] = p0; sc[nt][e0 + 1] = p1;
                sum += p0 + p1;
            }
            sum += __shfl_xor_sync(0xffffffff, sum, 1);
            sum += __shfl_xor_sync(0xffffffff, sum, 2);
            lrow[half] = lrow[half] * alpha + sum;
            mrow[half] = mnew;
#pragma unroll
            for (int nt = 0; nt < 16; nt++) {
                oc[nt][e0]     *= alpha;
                oc[nt][e0 + 1] *= alpha;
            }
        }

        CP_WAIT0();
        __syncthreads();

#pragma unroll
        for (int kb2 = 0; kb2 < 4; kb2++) {
            int nt0 = kb2 * 2, nt1 = nt0 + 1;
            uint32_t ph[4], pl[4];
#pragma unroll
            for (int r4 = 0; r4 < 4; r4++) {
                int nts = (r4 >> 1) ? nt1 : nt0;
                int eb = (r4 & 1) * 2;
                float x0 = sc[nts][eb], x1 = sc[nts][eb + 1];
                __half h0 = __float2half_rn(x0);
                __half h1 = __float2half_rn(x1);
                ph[r4] = packh2(h0, h1);
                pl[r4] = packh2(__float2half_rn(x0 - __half2float(h0)),
                                __float2half_rn(x1 - __half2float(h1)));
            }
            uint32_t vrow = kb2 * 16 * FSTR * 2;
#pragma unroll
            for (int np = 0; np < 8; np++) {
                uint32_t va = sb + 3 * FTB + v_add + vrow + np * 32;
                uint32_t v4h[4];
                LDSM_X4T(v4h[0], v4h[1], v4h[2], v4h[3], va);
                int nt = np * 2;
                MMA16816(oc[nt],     ph, v4h[0], v4h[1]);
                MMA16816(oc[nt + 1], ph, v4h[2], v4h[3]);
                MMA16816(oc[nt],     pl, v4h[0], v4h[1]);
                MMA16816(oc[nt + 1], pl, v4h[2], v4h[3]);
            }
        }
    }

#pragma unroll
    for (int half = 0; half < 2; half++) {
        float inv_l = 1.0f / lrow[half];
        int row = q0 + wm * 16 + (lane >> 2) + half * 8;
        size_t ob = (((size_t)b * Tt + row) * Hh + h) * HD;
#pragma unroll
        for (int nt = 0; nt < 16; nt++) {
            int d = nt * 8 + (lane & 3) * 2;
            float v0 = oc[nt][half * 2] * inv_l;
            float v1 = oc[nt][half * 2 + 1] * inv_l;
            __half h0 = __float2half_rn(v0);
            __half h1 = __float2half_rn(v1);
            *(__half2*)&Oh[ob + d] = __halves2half2(h0, h1);
            *(__half2*)&Ol[ob + d] = __halves2half2(
                __float2half_rn(v0 - __half2float(h0)),
                __float2half_rn(v1 - __half2float(h1)));
        }
    }
}

// ---------------- launch ----------------
extern "C" void kernel_launch(void* const* d_in, const int* in_sizes, int n_in,
                              void* d_out, int out_size)
{
    const float* x  = (const float*)d_in[0];
    const float* Wq = (const float*)d_in[1];
    const float* Wk = (const float*)d_in[2];
    const float* Wv = (const float*)d_in[3];
    const float* Wo = (const float*)d_in[4];
    float* out = (float*)d_out;

    __half *xsh, *xsl, *osh, *osl, *wqkvh, *woh;
    __half *qh, *ql, *kh, *vh;
    float2* rope;
    cudaGetSymbolAddress((void**)&xsh, g_xs_h);
    cudaGetSymbolAddress((void**)&xsl, g_xs_l);
    cudaGetSymbolAddress((void**)&osh, g_os_h);
    cudaGetSymbolAddress((void**)&osl, g_os_l);
    cudaGetSymbolAddress((void**)&wqkvh, g_wqkvt_h);
    cudaGetSymbolAddress((void**)&woh, g_wot_h);
    cudaGetSymbolAddress((void**)&qh, g_qh);
    cudaGetSymbolAddress((void**)&ql, g_ql);
    cudaGetSymbolAddress((void**)&kh, g_kh);
    cudaGetSymbolAddress((void**)&vh, g_vh);
    cudaGetSymbolAddress((void**)&rope, g_rope);

    const int M = Bsz * Tt;   // 4096
    const int n4 = M * Dd / 4;

    cudaFuncSetAttribute(mma_gemm, cudaFuncAttributeMaxDynamicSharedMemorySize, GEMM_SMEM);
    cudaFuncSetAttribute(flash_mma, cudaFuncAttributeMaxDynamicSharedMemorySize, FLASH_SMEM);

    tsplit_all_kernel<<<dim3(64, 64, 4), dim3(32, 8)>>>(Wq, Wk, Wv, Wo, wqkvh, woh);
    split_kernel<<<4096, 256>>>(x, xsh, xsl, n4);
    rope_table_kernel<<<(Tt * 64) / 256, 256>>>(rope);

    // fused QKV projection + RoPE + permute (Q split, K/V single)
    mma_gemm<<<dim3(NQKV / 128, M / 128), 128, GEMM_SMEM>>>(
        xsh, xsl, wqkvh, nullptr, M, NQKV, Dd, 1,
        rope, qh, ql, kh, vh);
    // flash attention (fp16 2-term)
    flash_mma<<<dim3(Tt / 64, Hh, Bsz), 128, FLASH_SMEM>>>(qh, ql, kh, vh, osh, osl);
    // output projection -> d_out
    mma_gemm<<<dim3(Dd / 128, M / 128), 128, GEMM_SMEM>>>(
        osh, osl, woh, out, M, Dd, Dd, 0,
        rope, qh, ql, kh, vh);
}

// round 15
// speedup vs baseline: 1.0597x; 1.0597x over previous
#include <cuda_runtime.h>
#include <cuda_fp16.h>
#include <cstdint>
#include <math.h>

#define Bsz 2
#define Tt 2048
#define Dd 2048
#define Hh 16
#define KVh 4
#define HD 128
#define GQ (Hh/KVh)
#define NQKV 3072

// ---------------- scratch ----------------
__device__ __half g_xs_h[(size_t)Bsz*Tt*Dd];
__device__ __half g_xs_l[(size_t)Bsz*Tt*Dd];
__device__ __half g_os_h[(size_t)Bsz*Tt*Dd];
__device__ __half g_os_l[(size_t)Bsz*Tt*Dd];
__device__ __half g_wqkvt_h[(size_t)NQKV*Dd];
__device__ __half g_wot_h[(size_t)Dd*Dd];

__device__ __half g_qh[(size_t)Bsz*Hh*Tt*HD];
__device__ __half g_ql[(size_t)Bsz*Hh*Tt*HD];
__device__ __half g_kh[(size_t)Bsz*KVh*Tt*HD];
__device__ __half g_vh[(size_t)Bsz*KVh*Tt*HD];

__device__ float2 g_rope[(size_t)Tt*64];

// ---------------- helpers ----------------
__device__ __forceinline__ uint32_t smem_u32(const void* p) {
    uint32_t a;
    asm("{ .reg .u64 t; cvta.to.shared.u64 t, %1; cvt.u32.u64 %0, t; }" : "=r"(a) : "l"(p));
    return a;
}

#define CP_ASYNC16(dst, src) \
    asm volatile("cp.async.cg.shared.global [%0], [%1], 16;" :: "r"(dst), "l"(src))
#define CP_COMMIT() asm volatile("cp.async.commit_group;")
#define CP_WAIT0()  asm volatile("cp.async.wait_group 0;")
#define CP_WAIT1()  asm volatile("cp.async.wait_group 1;")

#define LDSM_X4(r0, r1, r2, r3, addr) \
    asm volatile("ldmatrix.sync.aligned.m8n8.x4.shared.b16 {%0,%1,%2,%3}, [%4];" \
        : "=r"(r0), "=r"(r1), "=r"(r2), "=r"(r3) : "r"(addr))

#define LDSM_X4T(r0, r1, r2, r3, addr) \
    asm volatile("ldmatrix.sync.aligned.m8n8.x4.trans.shared.b16 {%0,%1,%2,%3}, [%4];" \
        : "=r"(r0), "=r"(r1), "=r"(r2), "=r"(r3) : "r"(addr))

#define MMA16816(c, a, b0, b1) \
    asm volatile("mma.sync.aligned.m16n8k16.row.col.f32.f16.f16.f32 " \
        "{%0,%1,%2,%3},{%4,%5,%6,%7},{%8,%9},{%0,%1,%2,%3};" \
        : "+f"((c)[0]), "+f"((c)[1]), "+f"((c)[2]), "+f"((c)[3]) \
        : "r"((a)[0]), "r"((a)[1]), "r"((a)[2]), "r"((a)[3]), "r"(b0), "r"(b1))

__device__ __forceinline__ uint32_t packh2(__half lo, __half hi) {
    union { __half2 v; uint32_t u; } cv;
    cv.v = __halves2half2(lo, hi);
    return cv.u;
}

// ---------------- conversion kernels ----------------
__global__ void split_kernel(const float* __restrict__ A,
                             __half* __restrict__ H,
                             __half* __restrict__ L, int n4)
{
    int i = blockIdx.x * blockDim.x + threadIdx.x;
    int stride = gridDim.x * blockDim.x;
    for (; i < n4; i += stride) {
        float4 a = ((const float4*)A)[i];
        __half h0 = __float2half_rn(a.x);
        __half h1 = __float2half_rn(a.y);
        __half h2 = __float2half_rn(a.z);
        __half h3 = __float2half_rn(a.w);
        __half l0 = __float2half_rn(a.x - __half2float(h0));
        __half l1 = __float2half_rn(a.y - __half2float(h1));
        __half l2 = __float2half_rn(a.z - __half2float(h2));
        __half l3 = __float2half_rn(a.w - __half2float(h3));
        ((__half2*)H)[2*i]   = __halves2half2(h0, h1);
        ((__half2*)H)[2*i+1] = __halves2half2(h2, h3);
        ((__half2*)L)[2*i]   = __halves2half2(l0, l1);
        ((__half2*)L)[2*i+1] = __halves2half2(l2, l3);
    }
}

__global__ void tsplit_all_kernel(
    const float* __restrict__ Wq, const float* __restrict__ Wk,
    const float* __restrict__ Wv, const float* __restrict__ Wo,
    __half* __restrict__ QKVh, __half* __restrict__ Oh)
{
    __shared__ float t[32][33];
    int z = blockIdx.z;
    const float* W;
    __half* Th;
    int N;
    if (z == 0)      { W = Wq; Th = QKVh;                      N = 2048; }
    else if (z == 1) { W = Wk; Th = QKVh + (size_t)2048 * Dd;  N = 512; }
    else if (z == 2) { W = Wv; Th = QKVh + (size_t)2560 * Dd;  N = 512; }
    else             { W = Wo; Th = Oh;                        N = 2048; }
    int n0 = blockIdx.x * 32, k0 = blockIdx.y * 32;
    if (n0 >= N) return;
    const int K = Dd;
    int tx = threadIdx.x, ty0 = threadIdx.y;
#pragma unroll
    for (int j = 0; j < 4; j++) {
        int ty = ty0 + j * 8;
        t[ty][tx] = W[(size_t)(k0 + ty) * N + n0 + tx];
    }
    __syncthreads();
#pragma unroll
    for (int j = 0; j < 4; j++) {
        int ty = ty0 + j * 8;
        Th[(size_t)(n0 + ty) * K + k0 + tx] = __float2half_rn(t[tx][ty]);
    }
}

__global__ void rope_table_kernel(float2* __restrict__ tab)
{
    int i = blockIdx.x * blockDim.x + threadIdx.x;
    int f = i & 63;
    int t = i >> 6;
    float inv = powf(10000.0f, -(float)f * (1.0f / 64.0f));
    float s, c;
    sincosf((float)t * inv, &s, &c);
    tab[i] = make_float2(s, c);
}

// ---------------- fp16 2-term GEMM: 128x128, 2-stage, 2 CTA/SM (R12 config) ----------------
#define KSP 40
#define TILE_B (128 * KSP * 2)        // 10240
#define STAGE_B (3 * TILE_B)          // 30720 (Ah, Al, Bh)
#define GEMM_SMEM (2 * STAGE_B)       // 61440

__global__ void __launch_bounds__(256, 2) mma_gemm(
    const __half* __restrict__ Ah, const __half* __restrict__ Al,
    const __half* __restrict__ Bh,
    float* __restrict__ C, int M, int N, int K, int mode,
    const float2* __restrict__ rope,
    __half* __restrict__ QH, __half* __restrict__ QL,
    __half* __restrict__ KH, __half* __restrict__ VH)
{
    extern __shared__ char sm[];
    uint32_t smem_base = smem_u32(sm);
    int tid = threadIdx.x;
    int wid = tid >> 5, lane = tid & 31;
    int wm = wid >> 2, wn = wid & 3;    // 2x4 grid, warp tile 64x32

    int m0 = blockIdx.y * 128, n0 = blockIdx.x * 128;
    int nstage = K / 32;

    float acc[4][4][4];
#pragma unroll
    for (int a = 0; a < 4; a++)
#pragma unroll
        for (int b = 0; b < 4; b++)
#pragma unroll
            for (int c = 0; c < 4; c++) acc[a][b][c] = 0.f;

    auto load_stage = [&](int kc, int s) {
        int kcol = kc * 32;
        uint32_t sb = smem_base + s * STAGE_B;
#pragma unroll
        for (int i = 0; i < 6; i++) {
            int c = tid + i * 256;
            int tile = c >> 9;           // 0=Ah 1=Al 2=Bh
            int cid = c & 511;
            int row = cid >> 2, kch = cid & 3;
            const __half* src;
            if (tile == 0)      src = Ah + (size_t)(m0 + row) * K + kcol + kch * 8;
            else if (tile == 1) src = Al + (size_t)(m0 + row) * K + kcol + kch * 8;
            else                src = Bh + (size_t)(n0 + row) * K + kcol + kch * 8;
            uint32_t dst = sb + tile * TILE_B + (row * KSP + kch * 8) * 2;
            CP_ASYNC16(dst, src);
        }
    };

    load_stage(0, 0); CP_COMMIT();

    uint32_t aoff = ((wm * 64 + (lane & 15)) * KSP + ((lane >> 4) << 3)) * 2;
    uint32_t boff = ((wn * 32 + ((lane >> 4) << 3) + (lane & 7)) * KSP + (((lane >> 3) & 1) << 3)) * 2;

    for (int kc = 0; kc < nstage; kc++) {
        CP_WAIT0();
        __syncthreads();
        if (kc + 1 < nstage) { load_stage(kc + 1, (kc + 1) & 1); CP_COMMIT(); }

        uint32_t sb = smem_base + (kc & 1) * STAGE_B;
        uint32_t aHi = sb + aoff;
        uint32_t bHi = sb + 2 * TILE_B + boff;

#pragma unroll
        for (int kk = 0; kk < 2; kk++) {
            uint32_t ko = kk * 32;
            uint32_t bh[2][4];
#pragma unroll
            for (int pr = 0; pr < 2; pr++)
                LDSM_X4(bh[pr][0], bh[pr][1], bh[pr][2], bh[pr][3], bHi + pr * 16 * KSP * 2 + ko);
#pragma unroll
            for (int mt = 0; mt < 4; mt++) {
                uint32_t ah4[4], al4[4];
                LDSM_X4(ah4[0], ah4[1], ah4[2], ah4[3], aHi + mt * 16 * KSP * 2 + ko);
                LDSM_X4(al4[0], al4[1], al4[2], al4[3], aHi + TILE_B + mt * 16 * KSP * 2 + ko);
#pragma unroll
                for (int nt = 0; nt < 4; nt++) {
                    int pr = nt >> 1, ix = (nt & 1) * 2;
                    MMA16816(acc[mt][nt], ah4, bh[pr][ix], bh[pr][ix + 1]);
                }
#pragma unroll
                for (int nt = 0; nt < 4; nt++) {
                    int pr = nt >> 1, ix = (nt & 1) * 2;
                    MMA16816(acc[mt][nt], al4, bh[pr][ix], bh[pr][ix + 1]);
                }
            }
        }
    }

    if (mode == 0) {
#pragma unroll
        for (int mt = 0; mt < 4; mt++)
#pragma unroll
            for (int nt = 0; nt < 4; nt++) {
                int row = m0 + wm * 64 + mt * 16 + (lane >> 2);
                int col = n0 + wn * 32 + nt * 8 + (lane & 3) * 2;
                *(float2*)&C[(size_t)row * N + col]       = make_float2(acc[mt][nt][0], acc[mt][nt][1]);
                *(float2*)&C[(size_t)(row + 8) * N + col] = make_float2(acc[mt][nt][2], acc[mt][nt][3]);
            }
    } else {
        const float qscale = 0.08838834764831845f;
#pragma unroll
        for (int mt = 0; mt < 4; mt++)
#pragma unroll
            for (int nt = 0; nt < 4; nt++) {
                int colp = n0 + wn * 32 + nt * 8 + (lane & 3) * 2;
#pragma unroll
                for (int rr = 0; rr < 2; rr++) {
                    int row = m0 + wm * 64 + mt * 16 + (lane >> 2) + rr * 8;
                    float x1 = acc[mt][nt][rr * 2];
                    float x2 = acc[mt][nt][rr * 2 + 1];
                    int t = row & (Tt - 1);
                    int b = row >> 11;
                    if (colp < 2048) {
                        int hh = colp >> 7, d = colp & 127, f = d >> 1;
                        float2 sc2 = rope[t * 64 + f];
                        float v1 = (x1 * sc2.y - x2 * sc2.x) * qscale;
                        float v2 = (x1 * sc2.x + x2 * sc2.y) * qscale;
                        size_t o = ((size_t)(b * Hh + hh) * Tt + t) * HD;
                        __half h1 = __float2half_rn(v1);
                        __half h2 = __float2half_rn(v2);
                        QH[o + f]      = h1;
                        QL[o + f]      = __float2half_rn(v1 - __half2float(h1));
                        QH[o + 64 + f] = h2;
                        QL[o + 64 + f] = __float2half_rn(v2 - __half2float(h2));
                    } else if (colp < 2560) {
                        int kvh = (colp - 2048) >> 7, d = (colp - 2048) & 127, f = d >> 1;
                        float2 sc2 = rope[t * 64 + f];
                        float v1 = x1 * sc2.y - x2 * sc2.x;
                        float v2 = x1 * sc2.x + x2 * sc2.y;
                        size_t o = ((size_t)(b * KVh + kvh) * Tt + t) * HD;
                        KH[o + f]      = __float2half_rn(v1);
                        KH[o + 64 + f] = __float2half_rn(v2);
                    } else {
                        int kvh = (colp - 2560) >> 7, d = (colp - 2560) & 127;
                        size_t o = ((size_t)(b * KVh + kvh) * Tt + t) * HD + d;
                        *(__half2*)&VH[o] = __halves2half2(__float2half_rn(x1), __float2half_rn(x2));
                    }
                }
            }
    }
}

// ---------------- Flash attention: QK 2-term, PV 1-term (P-lo dropped) ----------------
#define FSTR 136
#define FTB  (64 * FSTR * 2)          // 17408 per tile
#define FLASH_SMEM (4 * FTB)          // 69632

__global__ void __launch_bounds__(128, 3) flash_mma(
    const __half* __restrict__ Qh, const __half* __restrict__ Ql,
    const __half* __restrict__ Kh, const __half* __restrict__ Vh,
    __half* __restrict__ Oh, __half* __restrict__ Ol)
{
    extern __shared__ char sm[];
    uint32_t sb = smem_u32(sm);
    int tid = threadIdx.x, lane = tid & 31, wm = tid >> 5;
    int qt = gridDim.x - 1 - blockIdx.x;
    int h = blockIdx.y, b = blockIdx.z;
    int q0 = qt * 64;
    int kvh = h / GQ;

    const __half* Qhp = Qh + ((size_t)(b * Hh + h) * Tt + q0) * HD;
    const __half* Qlp = Ql + ((size_t)(b * Hh + h) * Tt + q0) * HD;
    const __half* Khp = Kh + (size_t)(b * KVh + kvh) * Tt * HD;
    const __half* Vhp = Vh + (size_t)(b * KVh + kvh) * Tt * HD;

#pragma unroll
    for (int i = 0; i < 8; i++) {
        int ch = tid + i * 128;
        int r = ch >> 4, c = ch & 15;
        uint32_t off = (uint32_t)(r * FSTR + c * 8) * 2;
        CP_ASYNC16(sb + off,       Qhp + (size_t)r * HD + c * 8);
        CP_ASYNC16(sb + FTB + off, Qlp + (size_t)r * HD + c * 8);
    }
    CP_COMMIT();

    float oc[16][4];
#pragma unroll
    for (int i = 0; i < 16; i++)
#pragma unroll
        for (int e = 0; e < 4; e++) oc[i][e] = 0.f;
    float mrow[2] = { -1e30f, -1e30f };
    float lrow[2] = { 0.f, 0.f };

    uint32_t q_add = (uint32_t)((wm * 16 + (lane & 15)) * FSTR + ((lane >> 4) << 3)) * 2;
    uint32_t k_add = (uint32_t)(((lane >> 4) * 8 + (lane & 7)) * FSTR + (((lane >> 3) & 1) << 3)) * 2;
    int vg = lane >> 3, vl8 = lane & 7;
    uint32_t v_add = (uint32_t)(((vg & 1) * 8 + vl8) * FSTR + ((vg >> 1) << 3)) * 2;

    int ntile = qt + 1;
    for (int j = 0; j < ntile; j++) {
        __syncthreads();
        const __half* kh = Khp + (size_t)j * 64 * HD;
        const __half* vh = Vhp + (size_t)j * 64 * HD;
#pragma unroll
        for (int i = 0; i < 8; i++) {
            int ch = tid + i * 128;
            int r = ch >> 4, c = ch & 15;
            uint32_t off = (uint32_t)(r * FSTR + c * 8) * 2;
            CP_ASYNC16(sb + 2 * FTB + off, kh + (size_t)r * HD + c * 8);
        }
        CP_COMMIT();
#pragma unroll
        for (int i = 0; i < 8; i++) {
            int ch = tid + i * 128;
            int r = ch >> 4, c = ch & 15;
            uint32_t off = (uint32_t)(r * FSTR + c * 8) * 2;
            CP_ASYNC16(sb + 3 * FTB + off, vh + (size_t)r * HD + c * 8);
        }
        CP_COMMIT();

        CP_WAIT1();
        __syncthreads();

        float sc[8][4];
#pragma unroll
        for (int nt = 0; nt < 8; nt++)
#pragma unroll
            for (int e = 0; e < 4; e++) sc[nt][e] = 0.f;

#pragma unroll
        for (int kb = 0; kb < 8; kb++) {
            uint32_t qh4[4], ql4[4];
            uint32_t ko = kb * 32;
            LDSM_X4(qh4[0], qh4[1], qh4[2], qh4[3], sb + q_add + ko);
            LDSM_X4(ql4[0], ql4[1], ql4[2], ql4[3], sb + FTB + q_add + ko);
            uint32_t kh4[4][4];
#pragma unroll
            for (int pr = 0; pr < 4; pr++) {
                uint32_t ra = pr * 16 * FSTR * 2 + ko;
                LDSM_X4(kh4[pr][0], kh4[pr][1], kh4[pr][2], kh4[pr][3], sb + 2 * FTB + k_add + ra);
            }
#pragma unroll
            for (int nt = 0; nt < 8; nt++) {
                int pr = nt >> 1, ix = (nt & 1) * 2;
                MMA16816(sc[nt], qh4, kh4[pr][ix], kh4[pr][ix + 1]);
            }
#pragma unroll
            for (int nt = 0; nt < 8; nt++) {
                int pr = nt >> 1, ix = (nt & 1) * 2;
                MMA16816(sc[nt], ql4, kh4[pr][ix], kh4[pr][ix + 1]);
            }
        }

        if (j == ntile - 1) {
            int row0 = q0 + wm * 16 + (lane >> 2);
#pragma unroll
            for (int nt = 0; nt < 8; nt++) {
                int col = j * 64 + nt * 8 + (lane & 3) * 2;
#pragma unroll
                for (int e = 0; e < 4; e++) {
                    int cc = col + (e & 1);
                    int rr = row0 + ((e >> 1) << 3);
                    if (cc > rr) sc[nt][e] = -1e30f;
                }
            }
        }

#pragma unroll
        for (int half = 0; half < 2; half++) {
            int e0 = half * 2;
            float mx = -1e30f;
#pragma unroll
            for (int nt = 0; nt < 8; nt++)
                mx = fmaxf(mx, fmaxf(sc[nt][e0], sc[nt][e0 + 1]));
            mx = fmaxf(mx, __shfl_xor_sync(0xffffffff, mx, 1));
            mx = fmaxf(mx, __shfl_xor_sync(0xffffffff, mx, 2));
            float mnew = fmaxf(mrow[half], mx);
            float alpha = __expf(mrow[half] - mnew);
            float sum = 0.f;
#pragma unroll
            for (int nt = 0; nt < 8; nt++) {
                float p0 = __expf(sc[nt][e0]     - mnew);
                float p1 = __expf(sc[nt][e0 + 1] - mnew);
                sc[nt][e0] = p0; sc[nt][e0 + 1] = p1;
                sum += p0 + p1;
            }
            sum += __shfl_xor_sync(0xffffffff, sum, 1);
            sum += __shfl_xor_sync(0xffffffff, sum, 2);
            lrow[half] = lrow[half] * alpha + sum;
            mrow[half] = mnew;
#pragma unroll
            for (int nt = 0; nt < 16; nt++) {
                oc[nt][e0]     *= alpha;
                oc[nt][e0 + 1] *= alpha;
            }
        }

        CP_WAIT0();
        __syncthreads();

        // ---- O += Ph @ Vh (single-term P) ----
#pragma unroll
        for (int kb2 = 0; kb2 < 4; kb2++) {
            int nt0 = kb2 * 2, nt1 = nt0 + 1;
            uint32_t ph[4];
#pragma unroll
            for (int r4 = 0; r4 < 4; r4++) {
                int nts = (r4 >> 1) ? nt1 : nt0;
                int eb = (r4 & 1) * 2;
                ph[r4] = packh2(__float2half_rn(sc[nts][eb]),
                                __float2half_rn(sc[nts][eb + 1]));
            }
            uint32_t vrow = kb2 * 16 * FSTR * 2;
#pragma unroll
            for (int np = 0; np < 8; np++) {
                uint32_t va = sb + 3 * FTB + v_add + vrow + np * 32;
                uint32_t v4h[4];
                LDSM_X4T(v4h[0], v4h[1], v4h[2], v4h[3], va);
                int nt = np * 2;
                MMA16816(oc[nt],     ph, v4h[0], v4h[1]);
                MMA16816(oc[nt + 1], ph, v4h[2], v4h[3]);
            }
        }
    }

#pragma unroll
    for (int half = 0; half < 2; half++) {
        float inv_l = 1.0f / lrow[half];
        int row = q0 + wm * 16 + (lane >> 2) + half * 8;
        size_t ob = (((size_t)b * Tt + row) * Hh + h) * HD;
#pragma unroll
        for (int nt = 0; nt < 16; nt++) {
            int d = nt * 8 + (lane & 3) * 2;
            float v0 = oc[nt][half * 2] * inv_l;
            float v1 = oc[nt][half * 2 + 1] * inv_l;
            __half h0 = __float2half_rn(v0);
            __half h1 = __float2half_rn(v1);
            *(__half2*)&Oh[ob + d] = __halves2half2(h0, h1);
            *(__half2*)&Ol[ob + d] = __halves2half2(
                __float2half_rn(v0 - __half2float(h0)),
                __float2half_rn(v1 - __half2float(h1)));
        }
    }
}

// ---------------- launch ----------------
extern "C" void kernel_launch(void* const* d_in, const int* in_sizes, int n_in,
                              void* d_out, int out_size)
{
    const float* x  = (const float*)d_in[0];
    const float* Wq = (const float*)d_in[1];
    const float* Wk = (const float*)d_in[2];
    const float* Wv = (const float*)d_in[3];
    const float* Wo = (const float*)d_in[4];
    float* out = (float*)d_out;

    __half *xsh, *xsl, *osh, *osl, *wqkvh, *woh;
    __half *qh, *ql, *kh, *vh;
    float2* rope;
    cudaGetSymbolAddress((void**)&xsh, g_xs_h);
    cudaGetSymbolAddress((void**)&xsl, g_xs_l);
    cudaGetSymbolAddress((void**)&osh, g_os_h);
    cudaGetSymbolAddress((void**)&osl, g_os_l);
    cudaGetSymbolAddress((void**)&wqkvh, g_wqkvt_h);
    cudaGetSymbolAddress((void**)&woh, g_wot_h);
    cudaGetSymbolAddress((void**)&qh, g_qh);
    cudaGetSymbolAddress((void**)&ql, g_ql);
    cudaGetSymbolAddress((void**)&kh, g_kh);
    cudaGetSymbolAddress((void**)&vh, g_vh);
    cudaGetSymbolAddress((void**)&rope, g_rope);

    const int M = Bsz * Tt;   // 4096
    const int n4 = M * Dd / 4;

    cudaFuncSetAttribute(mma_gemm, cudaFuncAttributeMaxDynamicSharedMemorySize, GEMM_SMEM);
    cudaFuncSetAttribute(flash_mma, cudaFuncAttributeMaxDynamicSharedMemorySize, FLASH_SMEM);

    tsplit_all_kernel<<<dim3(64, 64, 4), dim3(32, 8)>>>(Wq, Wk, Wv, Wo, wqkvh, woh);
    split_kernel<<<4096, 256>>>(x, xsh, xsl, n4);
    rope_table_kernel<<<(Tt * 64) / 256, 256>>>(rope);

    // fused QKV projection + RoPE + permute (Q split, K/V single)
    mma_gemm<<<dim3(NQKV / 128, M / 128), 256, GEMM_SMEM>>>(
        xsh, xsl, wqkvh, nullptr, M, NQKV, Dd, 1,
        rope, qh, ql, kh, vh);
    // flash attention
    flash_mma<<<dim3(Tt / 64, Hh, Bsz), 128, FLASH_SMEM>>>(qh, ql, kh, vh, osh, osl);
    // output projection -> d_out
    mma_gemm<<<dim3(Dd / 128, M / 128), 256, GEMM_SMEM>>>(
        osh, osl, woh, out, M, Dd, Dd, 0,
        rope, qh, ql, kh, vh);
}

// round 16
// speedup vs baseline: 1.1046x; 1.0423x over previous
#include <cuda_runtime.h>
#include <cuda_fp16.h>
#include <cstdint>
#include <math.h>

#define Bsz 2
#define Tt 2048
#define Dd 2048
#define Hh 16
#define KVh 4
#define HD 128
#define GQ (Hh/KVh)
#define NQKV 3072

// ---------------- scratch ----------------
__device__ __half g_xs_h[(size_t)Bsz*Tt*Dd];
__device__ __half g_xs_l[(size_t)Bsz*Tt*Dd];
__device__ __half g_os_h[(size_t)Bsz*Tt*Dd];
__device__ __half g_wqkvt_h[(size_t)NQKV*Dd];
__device__ __half g_wot_h[(size_t)Dd*Dd];

__device__ __half g_qh[(size_t)Bsz*Hh*Tt*HD];
__device__ __half g_ql[(size_t)Bsz*Hh*Tt*HD];
__device__ __half g_kh[(size_t)Bsz*KVh*Tt*HD];
__device__ __half g_vh[(size_t)Bsz*KVh*Tt*HD];

__device__ float2 g_rope[(size_t)Tt*64];

// ---------------- helpers ----------------
__device__ __forceinline__ uint32_t smem_u32(const void* p) {
    uint32_t a;
    asm("{ .reg .u64 t; cvta.to.shared.u64 t, %1; cvt.u32.u64 %0, t; }" : "=r"(a) : "l"(p));
    return a;
}

#define CP_ASYNC16(dst, src) \
    asm volatile("cp.async.cg.shared.global [%0], [%1], 16;" :: "r"(dst), "l"(src))
#define CP_COMMIT() asm volatile("cp.async.commit_group;")
#define CP_WAIT0()  asm volatile("cp.async.wait_group 0;")
#define CP_WAIT1()  asm volatile("cp.async.wait_group 1;")

#define LDSM_X4(r0, r1, r2, r3, addr) \
    asm volatile("ldmatrix.sync.aligned.m8n8.x4.shared.b16 {%0,%1,%2,%3}, [%4];" \
        : "=r"(r0), "=r"(r1), "=r"(r2), "=r"(r3) : "r"(addr))

#define LDSM_X4T(r0, r1, r2, r3, addr) \
    asm volatile("ldmatrix.sync.aligned.m8n8.x4.trans.shared.b16 {%0,%1,%2,%3}, [%4];" \
        : "=r"(r0), "=r"(r1), "=r"(r2), "=r"(r3) : "r"(addr))

#define MMA16816(c, a, b0, b1) \
    asm volatile("mma.sync.aligned.m16n8k16.row.col.f32.f16.f16.f32 " \
        "{%0,%1,%2,%3},{%4,%5,%6,%7},{%8,%9},{%0,%1,%2,%3};" \
        : "+f"((c)[0]), "+f"((c)[1]), "+f"((c)[2]), "+f"((c)[3]) \
        : "r"((a)[0]), "r"((a)[1]), "r"((a)[2]), "r"((a)[3]), "r"(b0), "r"(b1))

__device__ __forceinline__ uint32_t packh2(__half lo, __half hi) {
    union { __half2 v; uint32_t u; } cv;
    cv.v = __halves2half2(lo, hi);
    return cv.u;
}

// ---------------- conversion kernels ----------------
__global__ void split_kernel(const float* __restrict__ A,
                             __half* __restrict__ H,
                             __half* __restrict__ L, int n4)
{
    int i = blockIdx.x * blockDim.x + threadIdx.x;
    int stride = gridDim.x * blockDim.x;
    for (; i < n4; i += stride) {
        float4 a = ((const float4*)A)[i];
        __half h0 = __float2half_rn(a.x);
        __half h1 = __float2half_rn(a.y);
        __half h2 = __float2half_rn(a.z);
        __half h3 = __float2half_rn(a.w);
        __half l0 = __float2half_rn(a.x - __half2float(h0));
        __half l1 = __float2half_rn(a.y - __half2float(h1));
        __half l2 = __float2half_rn(a.z - __half2float(h2));
        __half l3 = __float2half_rn(a.w - __half2float(h3));
        ((__half2*)H)[2*i]   = __halves2half2(h0, h1);
        ((__half2*)H)[2*i+1] = __halves2half2(h2, h3);
        ((__half2*)L)[2*i]   = __halves2half2(l0, l1);
        ((__half2*)L)[2*i+1] = __halves2half2(l2, l3);
    }
}

__global__ void tsplit_all_kernel(
    const float* __restrict__ Wq, const float* __restrict__ Wk,
    const float* __restrict__ Wv, const float* __restrict__ Wo,
    __half* __restrict__ QKVh, __half* __restrict__ Oh)
{
    __shared__ float t[32][33];
    int z = blockIdx.z;
    const float* W;
    __half* Th;
    int N;
    if (z == 0)      { W = Wq; Th = QKVh;                      N = 2048; }
    else if (z == 1) { W = Wk; Th = QKVh + (size_t)2048 * Dd;  N = 512; }
    else if (z == 2) { W = Wv; Th = QKVh + (size_t)2560 * Dd;  N = 512; }
    else             { W = Wo; Th = Oh;                        N = 2048; }
    int n0 = blockIdx.x * 32, k0 = blockIdx.y * 32;
    if (n0 >= N) return;
    const int K = Dd;
    int tx = threadIdx.x, ty0 = threadIdx.y;
#pragma unroll
    for (int j = 0; j < 4; j++) {
        int ty = ty0 + j * 8;
        t[ty][tx] = W[(size_t)(k0 + ty) * N + n0 + tx];
    }
    __syncthreads();
#pragma unroll
    for (int j = 0; j < 4; j++) {
        int ty = ty0 + j * 8;
        Th[(size_t)(n0 + ty) * K + k0 + tx] = __float2half_rn(t[tx][ty]);
    }
}

__global__ void rope_table_kernel(float2* __restrict__ tab)
{
    int i = blockIdx.x * blockDim.x + threadIdx.x;
    int f = i & 63;
    int t = i >> 6;
    float inv = powf(10000.0f, -(float)f * (1.0f / 64.0f));
    float s, c;
    sincosf((float)t * inv, &s, &c);
    tab[i] = make_float2(s, c);
}

// ---------------- fp16 GEMM: 128x128, 2-stage, 2 CTA/SM; two_term selects A hi+lo ----------------
#define KSP 40
#define TILE_B (128 * KSP * 2)        // 10240
#define STAGE_B (3 * TILE_B)          // 30720 (Ah, Al, Bh)
#define GEMM_SMEM (2 * STAGE_B)       // 61440

__global__ void __launch_bounds__(256, 2) mma_gemm(
    const __half* __restrict__ Ah, const __half* __restrict__ Al,
    const __half* __restrict__ Bh,
    float* __restrict__ C, int M, int N, int K, int mode, int two_term,
    const float2* __restrict__ rope,
    __half* __restrict__ QH, __half* __restrict__ QL,
    __half* __restrict__ KH, __half* __restrict__ VH)
{
    extern __shared__ char sm[];
    uint32_t smem_base = smem_u32(sm);
    int tid = threadIdx.x;
    int wid = tid >> 5, lane = tid & 31;
    int wm = wid >> 2, wn = wid & 3;    // 2x4 grid, warp tile 64x32

    int m0 = blockIdx.y * 128, n0 = blockIdx.x * 128;
    int nstage = K / 32;

    float acc[4][4][4];
#pragma unroll
    for (int a = 0; a < 4; a++)
#pragma unroll
        for (int b = 0; b < 4; b++)
#pragma unroll
            for (int c = 0; c < 4; c++) acc[a][b][c] = 0.f;

    auto load_stage = [&](int kc, int s) {
        int kcol = kc * 32;
        uint32_t sb = smem_base + s * STAGE_B;
#pragma unroll
        for (int i = 0; i < 6; i++) {
            int c = tid + i * 256;
            int tile = c >> 9;           // 0=Ah 1=Al 2=Bh
            if (tile == 1 && !two_term) continue;
            int cid = c & 511;
            int row = cid >> 2, kch = cid & 3;
            const __half* src;
            if (tile == 0)      src = Ah + (size_t)(m0 + row) * K + kcol + kch * 8;
            else if (tile == 1) src = Al + (size_t)(m0 + row) * K + kcol + kch * 8;
            else                src = Bh + (size_t)(n0 + row) * K + kcol + kch * 8;
            uint32_t dst = sb + tile * TILE_B + (row * KSP + kch * 8) * 2;
            CP_ASYNC16(dst, src);
        }
    };

    load_stage(0, 0); CP_COMMIT();

    uint32_t aoff = ((wm * 64 + (lane & 15)) * KSP + ((lane >> 4) << 3)) * 2;
    uint32_t boff = ((wn * 32 + ((lane >> 4) << 3) + (lane & 7)) * KSP + (((lane >> 3) & 1) << 3)) * 2;

    for (int kc = 0; kc < nstage; kc++) {
        CP_WAIT0();
        __syncthreads();
        if (kc + 1 < nstage) { load_stage(kc + 1, (kc + 1) & 1); CP_COMMIT(); }

        uint32_t sb = smem_base + (kc & 1) * STAGE_B;
        uint32_t aHi = sb + aoff;
        uint32_t bHi = sb + 2 * TILE_B + boff;

#pragma unroll
        for (int kk = 0; kk < 2; kk++) {
            uint32_t ko = kk * 32;
            uint32_t bh[2][4];
#pragma unroll
            for (int pr = 0; pr < 2; pr++)
                LDSM_X4(bh[pr][0], bh[pr][1], bh[pr][2], bh[pr][3], bHi + pr * 16 * KSP * 2 + ko);
#pragma unroll
            for (int mt = 0; mt < 4; mt++) {
                uint32_t ah4[4];
                LDSM_X4(ah4[0], ah4[1], ah4[2], ah4[3], aHi + mt * 16 * KSP * 2 + ko);
#pragma unroll
                for (int nt = 0; nt < 4; nt++) {
                    int pr = nt >> 1, ix = (nt & 1) * 2;
                    MMA16816(acc[mt][nt], ah4, bh[pr][ix], bh[pr][ix + 1]);
                }
                if (two_term) {
                    uint32_t al4[4];
                    LDSM_X4(al4[0], al4[1], al4[2], al4[3], aHi + TILE_B + mt * 16 * KSP * 2 + ko);
#pragma unroll
                    for (int nt = 0; nt < 4; nt++) {
                        int pr = nt >> 1, ix = (nt & 1) * 2;
                        MMA16816(acc[mt][nt], al4, bh[pr][ix], bh[pr][ix + 1]);
                    }
                }
            }
        }
    }

    if (mode == 0) {
#pragma unroll
        for (int mt = 0; mt < 4; mt++)
#pragma unroll
            for (int nt = 0; nt < 4; nt++) {
                int row = m0 + wm * 64 + mt * 16 + (lane >> 2);
                int col = n0 + wn * 32 + nt * 8 + (lane & 3) * 2;
                *(float2*)&C[(size_t)row * N + col]       = make_float2(acc[mt][nt][0], acc[mt][nt][1]);
                *(float2*)&C[(size_t)(row + 8) * N + col] = make_float2(acc[mt][nt][2], acc[mt][nt][3]);
            }
    } else {
        const float qscale = 0.08838834764831845f;
#pragma unroll
        for (int mt = 0; mt < 4; mt++)
#pragma unroll
            for (int nt = 0; nt < 4; nt++) {
                int colp = n0 + wn * 32 + nt * 8 + (lane & 3) * 2;
#pragma unroll
                for (int rr = 0; rr < 2; rr++) {
                    int row = m0 + wm * 64 + mt * 16 + (lane >> 2) + rr * 8;
                    float x1 = acc[mt][nt][rr * 2];
                    float x2 = acc[mt][nt][rr * 2 + 1];
                    int t = row & (Tt - 1);
                    int b = row >> 11;
                    if (colp < 2048) {
                        int hh = colp >> 7, d = colp & 127, f = d >> 1;
                        float2 sc2 = rope[t * 64 + f];
                        float v1 = (x1 * sc2.y - x2 * sc2.x) * qscale;
                        float v2 = (x1 * sc2.x + x2 * sc2.y) * qscale;
                        size_t o = ((size_t)(b * Hh + hh) * Tt + t) * HD;
                        __half h1 = __float2half_rn(v1);
                        __half h2 = __float2half_rn(v2);
                        QH[o + f]      = h1;
                        QL[o + f]      = __float2half_rn(v1 - __half2float(h1));
                        QH[o + 64 + f] = h2;
                        QL[o + 64 + f] = __float2half_rn(v2 - __half2float(h2));
                    } else if (colp < 2560) {
                        int kvh = (colp - 2048) >> 7, d = (colp - 2048) & 127, f = d >> 1;
                        float2 sc2 = rope[t * 64 + f];
                        float v1 = x1 * sc2.y - x2 * sc2.x;
                        float v2 = x1 * sc2.x + x2 * sc2.y;
                        size_t o = ((size_t)(b * KVh + kvh) * Tt + t) * HD;
                        KH[o + f]      = __float2half_rn(v1);
                        KH[o + 64 + f] = __float2half_rn(v2);
                    } else {
                        int kvh = (colp - 2560) >> 7, d = (colp - 2560) & 127;
                        size_t o = ((size_t)(b * KVh + kvh) * Tt + t) * HD + d;
                        *(__half2*)&VH[o] = __halves2half2(__float2half_rn(x1), __float2half_rn(x2));
                    }
                }
            }
    }
}

// ---------------- Flash attention: QK 2-term, PV 1-term, O single fp16 ----------------
#define FSTR 136
#define FTB  (64 * FSTR * 2)          // 17408 per tile
#define FLASH_SMEM (4 * FTB)          // 69632

__global__ void __launch_bounds__(128, 3) flash_mma(
    const __half* __restrict__ Qh, const __half* __restrict__ Ql,
    const __half* __restrict__ Kh, const __half* __restrict__ Vh,
    __half* __restrict__ Oh)
{
    extern __shared__ char sm[];
    uint32_t sb = smem_u32(sm);
    int tid = threadIdx.x, lane = tid & 31, wm = tid >> 5;
    int qt = gridDim.x - 1 - blockIdx.x;
    int h = blockIdx.y, b = blockIdx.z;
    int q0 = qt * 64;
    int kvh = h / GQ;

    const __half* Qhp = Qh + ((size_t)(b * Hh + h) * Tt + q0) * HD;
    const __half* Qlp = Ql + ((size_t)(b * Hh + h) * Tt + q0) * HD;
    const __half* Khp = Kh + (size_t)(b * KVh + kvh) * Tt * HD;
    const __half* Vhp = Vh + (size_t)(b * KVh + kvh) * Tt * HD;

#pragma unroll
    for (int i = 0; i < 8; i++) {
        int ch = tid + i * 128;
        int r = ch >> 4, c = ch & 15;
        uint32_t off = (uint32_t)(r * FSTR + c * 8) * 2;
        CP_ASYNC16(sb + off,       Qhp + (size_t)r * HD + c * 8);
        CP_ASYNC16(sb + FTB + off, Qlp + (size_t)r * HD + c * 8);
    }
    CP_COMMIT();

    float oc[16][4];
#pragma unroll
    for (int i = 0; i < 16; i++)
#pragma unroll
        for (int e = 0; e < 4; e++) oc[i][e] = 0.f;
    float mrow[2] = { -1e30f, -1e30f };
    float lrow[2] = { 0.f, 0.f };

    uint32_t q_add = (uint32_t)((wm * 16 + (lane & 15)) * FSTR + ((lane >> 4) << 3)) * 2;
    uint32_t k_add = (uint32_t)(((lane >> 4) * 8 + (lane & 7)) * FSTR + (((lane >> 3) & 1) << 3)) * 2;
    int vg = lane >> 3, vl8 = lane & 7;
    uint32_t v_add = (uint32_t)(((vg & 1) * 8 + vl8) * FSTR + ((vg >> 1) << 3)) * 2;

    int ntile = qt + 1;
    for (int j = 0; j < ntile; j++) {
        __syncthreads();
        const __half* kh = Khp + (size_t)j * 64 * HD;
        const __half* vh = Vhp + (size_t)j * 64 * HD;
#pragma unroll
        for (int i = 0; i < 8; i++) {
            int ch = tid + i * 128;
            int r = ch >> 4, c = ch & 15;
            uint32_t off = (uint32_t)(r * FSTR + c * 8) * 2;
            CP_ASYNC16(sb + 2 * FTB + off, kh + (size_t)r * HD + c * 8);
        }
        CP_COMMIT();
#pragma unroll
        for (int i = 0; i < 8; i++) {
            int ch = tid + i * 128;
            int r = ch >> 4, c = ch & 15;
            uint32_t off = (uint32_t)(r * FSTR + c * 8) * 2;
            CP_ASYNC16(sb + 3 * FTB + off, vh + (size_t)r * HD + c * 8);
        }
        CP_COMMIT();

        CP_WAIT1();
        __syncthreads();

        float sc[8][4];
#pragma unroll
        for (int nt = 0; nt < 8; nt++)
#pragma unroll
            for (int e = 0; e < 4; e++) sc[nt][e] = 0.f;

#pragma unroll
        for (int kb = 0; kb < 8; kb++) {
            uint32_t qh4[4], ql4[4];
            uint32_t ko = kb * 32;
            LDSM_X4(qh4[0], qh4[1], qh4[2], qh4[3], sb + q_add + ko);
            LDSM_X4(ql4[0], ql4[1], ql4[2], ql4[3], sb + FTB + q_add + ko);
            uint32_t kh4[4][4];
#pragma unroll
            for (int pr = 0; pr < 4; pr++) {
                uint32_t ra = pr * 16 * FSTR * 2 + ko;
                LDSM_X4(kh4[pr][0], kh4[pr][1], kh4[pr][2], kh4[pr][3], sb + 2 * FTB + k_add + ra);
            }
#pragma unroll
            for (int nt = 0; nt < 8; nt++) {
                int pr = nt >> 1, ix = (nt & 1) * 2;
                MMA16816(sc[nt], qh4, kh4[pr][ix], kh4[pr][ix + 1]);
            }
#pragma unroll
            for (int nt = 0; nt < 8; nt++) {
                int pr = nt >> 1, ix = (nt & 1) * 2;
                MMA16816(sc[nt], ql4, kh4[pr][ix], kh4[pr][ix + 1]);
            }
        }

        if (j == ntile - 1) {
            int row0 = q0 + wm * 16 + (lane >> 2);
#pragma unroll
            for (int nt = 0; nt < 8; nt++) {
                int col = j * 64 + nt * 8 + (lane & 3) * 2;
#pragma unroll
                for (int e = 0; e < 4; e++) {
                    int cc = col + (e & 1);
                    int rr = row0 + ((e >> 1) << 3);
                    if (cc > rr) sc[nt][e] = -1e30f;
                }
            }
        }

#pragma unroll
        for (int half = 0; half < 2; half++) {
            int e0 = half * 2;
            float mx = -1e30f;
#pragma unroll
            for (int nt = 0; nt < 8; nt++)
                mx = fmaxf(mx, fmaxf(sc[nt][e0], sc[nt][e0 + 1]));
            mx = fmaxf(mx, __shfl_xor_sync(0xffffffff, mx, 1));
            mx = fmaxf(mx, __shfl_xor_sync(0xffffffff, mx, 2));
            float mnew = fmaxf(mrow[half], mx);
            float alpha = __expf(mrow[half] - mnew);
            float sum = 0.f;
#pragma unroll
            for (int nt = 0; nt < 8; nt++) {
                float p0 = __expf(sc[nt][e0]     - mnew);
                float p1 = __expf(sc[nt][e0 + 1] - mnew);
                sc[nt][e0] = p0; sc[nt][e0 + 1] = p1;
                sum += p0 + p1;
            }
            sum += __shfl_xor_sync(0xffffffff, sum, 1);
            sum += __shfl_xor_sync(0xffffffff, sum, 2);
            lrow[half] = lrow[half] * alpha + sum;
            mrow[half] = mnew;
#pragma unroll
            for (int nt = 0; nt < 16; nt++) {
                oc[nt][e0]     *= alpha;
                oc[nt][e0 + 1] *= alpha;
            }
        }

        CP_WAIT0();
        __syncthreads();

#pragma unroll
        for (int kb2 = 0; kb2 < 4; kb2++) {
            int nt0 = kb2 * 2, nt1 = nt0 + 1;
            uint32_t ph[4];
#pragma unroll
            for (int r4 = 0; r4 < 4; r4++) {
                int nts = (r4 >> 1) ? nt1 : nt0;
                int eb = (r4 & 1) * 2;
                ph[r4] = packh2(__float2half_rn(sc[nts][eb]),
                                __float2half_rn(sc[nts][eb + 1]));
            }
            uint32_t vrow = kb2 * 16 * FSTR * 2;
#pragma unroll
            for (int np = 0; np < 8; np++) {
                uint32_t va = sb + 3 * FTB + v_add + vrow + np * 32;
                uint32_t v4h[4];
                LDSM_X4T(v4h[0], v4h[1], v4h[2], v4h[3], va);
                int nt = np * 2;
                MMA16816(oc[nt],     ph, v4h[0], v4h[1]);
                MMA16816(oc[nt + 1], ph, v4h[2], v4h[3]);
            }
        }
    }

#pragma unroll
    for (int half = 0; half < 2; half++) {
        float inv_l = 1.0f / lrow[half];
        int row = q0 + wm * 16 + (lane >> 2) + half * 8;
        size_t ob = (((size_t)b * Tt + row) * Hh + h) * HD;
#pragma unroll
        for (int nt = 0; nt < 16; nt++) {
            int d = nt * 8 + (lane & 3) * 2;
            float v0 = oc[nt][half * 2] * inv_l;
            float v1 = oc[nt][half * 2 + 1] * inv_l;
            *(__half2*)&Oh[ob + d] = __halves2half2(__float2half_rn(v0),
                                                    __float2half_rn(v1));
        }
    }
}

// ---------------- launch ----------------
extern "C" void kernel_launch(void* const* d_in, const int* in_sizes, int n_in,
                              void* d_out, int out_size)
{
    const float* x  = (const float*)d_in[0];
    const float* Wq = (const float*)d_in[1];
    const float* Wk = (const float*)d_in[2];
    const float* Wv = (const float*)d_in[3];
    const float* Wo = (const float*)d_in[4];
    float* out = (float*)d_out;

    __half *xsh, *xsl, *osh, *wqkvh, *woh;
    __half *qh, *ql, *kh, *vh;
    float2* rope;
    cudaGetSymbolAddress((void**)&xsh, g_xs_h);
    cudaGetSymbolAddress((void**)&xsl, g_xs_l);
    cudaGetSymbolAddress((void**)&osh, g_os_h);
    cudaGetSymbolAddress((void**)&wqkvh, g_wqkvt_h);
    cudaGetSymbolAddress((void**)&woh, g_wot_h);
    cudaGetSymbolAddress((void**)&qh, g_qh);
    cudaGetSymbolAddress((void**)&ql, g_ql);
    cudaGetSymbolAddress((void**)&kh, g_kh);
    cudaGetSymbolAddress((void**)&vh, g_vh);
    cudaGetSymbolAddress((void**)&rope, g_rope);

    const int M = Bsz * Tt;   // 4096
    const int n4 = M * Dd / 4;

    cudaFuncSetAttribute(mma_gemm, cudaFuncAttributeMaxDynamicSharedMemorySize, GEMM_SMEM);
    cudaFuncSetAttribute(flash_mma, cudaFuncAttributeMaxDynamicSharedMemorySize, FLASH_SMEM);

    tsplit_all_kernel<<<dim3(64, 64, 4), dim3(32, 8)>>>(Wq, Wk, Wv, Wo, wqkvh, woh);
    split_kernel<<<4096, 256>>>(x, xsh, xsl, n4);
    rope_table_kernel<<<(Tt * 64) / 256, 256>>>(rope);

    // fused QKV projection + RoPE + permute (x 2-term)
    mma_gemm<<<dim3(NQKV / 128, M / 128), 256, GEMM_SMEM>>>(
        xsh, xsl, wqkvh, nullptr, M, NQKV, Dd, 1, 1,
        rope, qh, ql, kh, vh);
    // flash attention (O single fp16)
    flash_mma<<<dim3(Tt / 64, Hh, Bsz), 128, FLASH_SMEM>>>(qh, ql, kh, vh, osh);
    // output projection -> d_out (O 1-term)
    mma_gemm<<<dim3(Dd / 128, M / 128), 256, GEMM_SMEM>>>(
        osh, osh, woh, out, M, Dd, Dd, 0, 0,
        rope, qh, ql, kh, vh);
}

// round 17
// speedup vs baseline: 1.1644x; 1.0542x over previous
#include <cuda_runtime.h>
#include <cuda_fp16.h>
#include <cstdint>
#include <math.h>

#define Bsz 2
#define Tt 2048
#define Dd 2048
#define Hh 16
#define KVh 4
#define HD 128
#define GQ (Hh/KVh)
#define NQKV 3072

// ---------------- scratch ----------------
__device__ __half g_xs_h[(size_t)Bsz*Tt*Dd];
__device__ __half g_os_h[(size_t)Bsz*Tt*Dd];
__device__ __half g_wqkvt_h[(size_t)NQKV*Dd];
__device__ __half g_wot_h[(size_t)Dd*Dd];

__device__ __half g_qh[(size_t)Bsz*Hh*Tt*HD];
__device__ __half g_ql[(size_t)Bsz*Hh*Tt*HD];
__device__ __half g_kh[(size_t)Bsz*KVh*Tt*HD];
__device__ __half g_vh[(size_t)Bsz*KVh*Tt*HD];

__device__ float2 g_rope[(size_t)Tt*64];

// ---------------- helpers ----------------
__device__ __forceinline__ uint32_t smem_u32(const void* p) {
    uint32_t a;
    asm("{ .reg .u64 t; cvta.to.shared.u64 t, %1; cvt.u32.u64 %0, t; }" : "=r"(a) : "l"(p));
    return a;
}

#define CP_ASYNC16(dst, src) \
    asm volatile("cp.async.cg.shared.global [%0], [%1], 16;" :: "r"(dst), "l"(src))
#define CP_COMMIT() asm volatile("cp.async.commit_group;")
#define CP_WAIT0()  asm volatile("cp.async.wait_group 0;")
#define CP_WAIT1()  asm volatile("cp.async.wait_group 1;")

#define LDSM_X4(r0, r1, r2, r3, addr) \
    asm volatile("ldmatrix.sync.aligned.m8n8.x4.shared.b16 {%0,%1,%2,%3}, [%4];" \
        : "=r"(r0), "=r"(r1), "=r"(r2), "=r"(r3) : "r"(addr))

#define LDSM_X4T(r0, r1, r2, r3, addr) \
    asm volatile("ldmatrix.sync.aligned.m8n8.x4.trans.shared.b16 {%0,%1,%2,%3}, [%4];" \
        : "=r"(r0), "=r"(r1), "=r"(r2), "=r"(r3) : "r"(addr))

#define MMA16816(c, a, b0, b1) \
    asm volatile("mma.sync.aligned.m16n8k16.row.col.f32.f16.f16.f32 " \
        "{%0,%1,%2,%3},{%4,%5,%6,%7},{%8,%9},{%0,%1,%2,%3};" \
        : "+f"((c)[0]), "+f"((c)[1]), "+f"((c)[2]), "+f"((c)[3]) \
        : "r"((a)[0]), "r"((a)[1]), "r"((a)[2]), "r"((a)[3]), "r"(b0), "r"(b1))

__device__ __forceinline__ uint32_t packh2(__half lo, __half hi) {
    union { __half2 v; uint32_t u; } cv;
    cv.v = __halves2half2(lo, hi);
    return cv.u;
}

// ---------------- conversion kernels ----------------
// fp32 -> fp16 (single term)
__global__ void convert_kernel(const float* __restrict__ A,
                               __half* __restrict__ H, int n4)
{
    int i = blockIdx.x * blockDim.x + threadIdx.x;
    int stride = gridDim.x * blockDim.x;
    for (; i < n4; i += stride) {
        float4 a = ((const float4*)A)[i];
        ((__half2*)H)[2*i]   = __halves2half2(__float2half_rn(a.x), __float2half_rn(a.y));
        ((__half2*)H)[2*i+1] = __halves2half2(__float2half_rn(a.z), __float2half_rn(a.w));
    }
}

__global__ void tsplit_all_kernel(
    const float* __restrict__ Wq, const float* __restrict__ Wk,
    const float* __restrict__ Wv, const float* __restrict__ Wo,
    __half* __restrict__ QKVh, __half* __restrict__ Oh)
{
    __shared__ float t[32][33];
    int z = blockIdx.z;
    const float* W;
    __half* Th;
    int N;
    if (z == 0)      { W = Wq; Th = QKVh;                      N = 2048; }
    else if (z == 1) { W = Wk; Th = QKVh + (size_t)2048 * Dd;  N = 512; }
    else if (z == 2) { W = Wv; Th = QKVh + (size_t)2560 * Dd;  N = 512; }
    else             { W = Wo; Th = Oh;                        N = 2048; }
    int n0 = blockIdx.x * 32, k0 = blockIdx.y * 32;
    if (n0 >= N) return;
    const int K = Dd;
    int tx = threadIdx.x, ty0 = threadIdx.y;
#pragma unroll
    for (int j = 0; j < 4; j++) {
        int ty = ty0 + j * 8;
        t[ty][tx] = W[(size_t)(k0 + ty) * N + n0 + tx];
    }
    __syncthreads();
#pragma unroll
    for (int j = 0; j < 4; j++) {
        int ty = ty0 + j * 8;
        Th[(size_t)(n0 + ty) * K + k0 + tx] = __float2half_rn(t[tx][ty]);
    }
}

__global__ void rope_table_kernel(float2* __restrict__ tab)
{
    int i = blockIdx.x * blockDim.x + threadIdx.x;
    int f = i & 63;
    int t = i >> 6;
    float inv = powf(10000.0f, -(float)f * (1.0f / 64.0f));
    float s, c;
    sincosf((float)t * inv, &s, &c);
    tab[i] = make_float2(s, c);
}

// ---------------- fp16 GEMM: 128x128, 2-stage, 2 CTA/SM; two_term selects A hi+lo ----------------
#define KSP 40
#define TILE_B (128 * KSP * 2)        // 10240
#define STAGE_B (3 * TILE_B)          // 30720 (Ah, Al, Bh)
#define GEMM_SMEM (2 * STAGE_B)       // 61440

__global__ void __launch_bounds__(256, 2) mma_gemm(
    const __half* __restrict__ Ah, const __half* __restrict__ Al,
    const __half* __restrict__ Bh,
    float* __restrict__ C, int M, int N, int K, int mode, int two_term,
    const float2* __restrict__ rope,
    __half* __restrict__ QH, __half* __restrict__ QL,
    __half* __restrict__ KH, __half* __restrict__ VH)
{
    extern __shared__ char sm[];
    uint32_t smem_base = smem_u32(sm);
    int tid = threadIdx.x;
    int wid = tid >> 5, lane = tid & 31;
    int wm = wid >> 2, wn = wid & 3;    // 2x4 grid, warp tile 64x32

    int m0 = blockIdx.y * 128, n0 = blockIdx.x * 128;
    int nstage = K / 32;

    float acc[4][4][4];
#pragma unroll
    for (int a = 0; a < 4; a++)
#pragma unroll
        for (int b = 0; b < 4; b++)
#pragma unroll
            for (int c = 0; c < 4; c++) acc[a][b][c] = 0.f;

    auto load_stage = [&](int kc, int s) {
        int kcol = kc * 32;
        uint32_t sb = smem_base + s * STAGE_B;
#pragma unroll
        for (int i = 0; i < 6; i++) {
            int c = tid + i * 256;
            int tile = c >> 9;           // 0=Ah 1=Al 2=Bh
            if (tile == 1 && !two_term) continue;
            int cid = c & 511;
            int row = cid >> 2, kch = cid & 3;
            const __half* src;
            if (tile == 0)      src = Ah + (size_t)(m0 + row) * K + kcol + kch * 8;
            else if (tile == 1) src = Al + (size_t)(m0 + row) * K + kcol + kch * 8;
            else                src = Bh + (size_t)(n0 + row) * K + kcol + kch * 8;
            uint32_t dst = sb + tile * TILE_B + (row * KSP + kch * 8) * 2;
            CP_ASYNC16(dst, src);
        }
    };

    load_stage(0, 0); CP_COMMIT();

    uint32_t aoff = ((wm * 64 + (lane & 15)) * KSP + ((lane >> 4) << 3)) * 2;
    uint32_t boff = ((wn * 32 + ((lane >> 4) << 3) + (lane & 7)) * KSP + (((lane >> 3) & 1) << 3)) * 2;

    for (int kc = 0; kc < nstage; kc++) {
        CP_WAIT0();
        __syncthreads();
        if (kc + 1 < nstage) { load_stage(kc + 1, (kc + 1) & 1); CP_COMMIT(); }

        uint32_t sb = smem_base + (kc & 1) * STAGE_B;
        uint32_t aHi = sb + aoff;
        uint32_t bHi = sb + 2 * TILE_B + boff;

#pragma unroll
        for (int kk = 0; kk < 2; kk++) {
            uint32_t ko = kk * 32;
            uint32_t bh[2][4];
#pragma unroll
            for (int pr = 0; pr < 2; pr++)
                LDSM_X4(bh[pr][0], bh[pr][1], bh[pr][2], bh[pr][3], bHi + pr * 16 * KSP * 2 + ko);
#pragma unroll
            for (int mt = 0; mt < 4; mt++) {
                uint32_t ah4[4];
                LDSM_X4(ah4[0], ah4[1], ah4[2], ah4[3], aHi + mt * 16 * KSP * 2 + ko);
#pragma unroll
                for (int nt = 0; nt < 4; nt++) {
                    int pr = nt >> 1, ix = (nt & 1) * 2;
                    MMA16816(acc[mt][nt], ah4, bh[pr][ix], bh[pr][ix + 1]);
                }
                if (two_term) {
                    uint32_t al4[4];
                    LDSM_X4(al4[0], al4[1], al4[2], al4[3], aHi + TILE_B + mt * 16 * KSP * 2 + ko);
#pragma unroll
                    for (int nt = 0; nt < 4; nt++) {
                        int pr = nt >> 1, ix = (nt & 1) * 2;
                        MMA16816(acc[mt][nt], al4, bh[pr][ix], bh[pr][ix + 1]);
                    }
                }
            }
        }
    }

    if (mode == 0) {
#pragma unroll
        for (int mt = 0; mt < 4; mt++)
#pragma unroll
            for (int nt = 0; nt < 4; nt++) {
                int row = m0 + wm * 64 + mt * 16 + (lane >> 2);
                int col = n0 + wn * 32 + nt * 8 + (lane & 3) * 2;
                *(float2*)&C[(size_t)row * N + col]       = make_float2(acc[mt][nt][0], acc[mt][nt][1]);
                *(float2*)&C[(size_t)(row + 8) * N + col] = make_float2(acc[mt][nt][2], acc[mt][nt][3]);
            }
    } else {
        const float qscale = 0.08838834764831845f;
#pragma unroll
        for (int mt = 0; mt < 4; mt++)
#pragma unroll
            for (int nt = 0; nt < 4; nt++) {
                int colp = n0 + wn * 32 + nt * 8 + (lane & 3) * 2;
#pragma unroll
                for (int rr = 0; rr < 2; rr++) {
                    int row = m0 + wm * 64 + mt * 16 + (lane >> 2) + rr * 8;
                    float x1 = acc[mt][nt][rr * 2];
                    float x2 = acc[mt][nt][rr * 2 + 1];
                    int t = row & (Tt - 1);
                    int b = row >> 11;
                    if (colp < 2048) {
                        int hh = colp >> 7, d = colp & 127, f = d >> 1;
                        float2 sc2 = rope[t * 64 + f];
                        float v1 = (x1 * sc2.y - x2 * sc2.x) * qscale;
                        float v2 = (x1 * sc2.x + x2 * sc2.y) * qscale;
                        size_t o = ((size_t)(b * Hh + hh) * Tt + t) * HD;
                        __half h1 = __float2half_rn(v1);
                        __half h2 = __float2half_rn(v2);
                        QH[o + f]      = h1;
                        QL[o + f]      = __float2half_rn(v1 - __half2float(h1));
                        QH[o + 64 + f] = h2;
                        QL[o + 64 + f] = __float2half_rn(v2 - __half2float(h2));
                    } else if (colp < 2560) {
                        int kvh = (colp - 2048) >> 7, d = (colp - 2048) & 127, f = d >> 1;
                        float2 sc2 = rope[t * 64 + f];
                        float v1 = x1 * sc2.y - x2 * sc2.x;
                        float v2 = x1 * sc2.x + x2 * sc2.y;
                        size_t o = ((size_t)(b * KVh + kvh) * Tt + t) * HD;
                        KH[o + f]      = __float2half_rn(v1);
                        KH[o + 64 + f] = __float2half_rn(v2);
                    } else {
                        int kvh = (colp - 2560) >> 7, d = (colp - 2560) & 127;
                        size_t o = ((size_t)(b * KVh + kvh) * Tt + t) * HD + d;
                        *(__half2*)&VH[o] = __halves2half2(__float2half_rn(x1), __float2half_rn(x2));
                    }
                }
            }
    }
}

// ---------------- Flash attention: QK 2-term, PV 1-term, O single fp16 ----------------
#define FSTR 136
#define FTB  (64 * FSTR * 2)          // 17408 per tile
#define FLASH_SMEM (4 * FTB)          // 69632

__global__ void __launch_bounds__(128, 3) flash_mma(
    const __half* __restrict__ Qh, const __half* __restrict__ Ql,
    const __half* __restrict__ Kh, const __half* __restrict__ Vh,
    __half* __restrict__ Oh)
{
    extern __shared__ char sm[];
    uint32_t sb = smem_u32(sm);
    int tid = threadIdx.x, lane = tid & 31, wm = tid >> 5;
    int qt = gridDim.x - 1 - blockIdx.x;
    int h = blockIdx.y, b = blockIdx.z;
    int q0 = qt * 64;
    int kvh = h / GQ;

    const __half* Qhp = Qh + ((size_t)(b * Hh + h) * Tt + q0) * HD;
    const __half* Qlp = Ql + ((size_t)(b * Hh + h) * Tt + q0) * HD;
    const __half* Khp = Kh + (size_t)(b * KVh + kvh) * Tt * HD;
    const __half* Vhp = Vh + (size_t)(b * KVh + kvh) * Tt * HD;

#pragma unroll
    for (int i = 0; i < 8; i++) {
        int ch = tid + i * 128;
        int r = ch >> 4, c = ch & 15;
        uint32_t off = (uint32_t)(r * FSTR + c * 8) * 2;
        CP_ASYNC16(sb + off,       Qhp + (size_t)r * HD + c * 8);
        CP_ASYNC16(sb + FTB + off, Qlp + (size_t)r * HD + c * 8);
    }
    CP_COMMIT();

    float oc[16][4];
#pragma unroll
    for (int i = 0; i < 16; i++)
#pragma unroll
        for (int e = 0; e < 4; e++) oc[i][e] = 0.f;
    float mrow[2] = { -1e30f, -1e30f };
    float lrow[2] = { 0.f, 0.f };

    uint32_t q_add = (uint32_t)((wm * 16 + (lane & 15)) * FSTR + ((lane >> 4) << 3)) * 2;
    uint32_t k_add = (uint32_t)(((lane >> 4) * 8 + (lane & 7)) * FSTR + (((lane >> 3) & 1) << 3)) * 2;
    int vg = lane >> 3, vl8 = lane & 7;
    uint32_t v_add = (uint32_t)(((vg & 1) * 8 + vl8) * FSTR + ((vg >> 1) << 3)) * 2;

    int ntile = qt + 1;
    for (int j = 0; j < ntile; j++) {
        __syncthreads();
        const __half* kh = Khp + (size_t)j * 64 * HD;
        const __half* vh = Vhp + (size_t)j * 64 * HD;
#pragma unroll
        for (int i = 0; i < 8; i++) {
            int ch = tid + i * 128;
            int r = ch >> 4, c = ch & 15;
            uint32_t off = (uint32_t)(r * FSTR + c * 8) * 2;
            CP_ASYNC16(sb + 2 * FTB + off, kh + (size_t)r * HD + c * 8);
        }
        CP_COMMIT();
#pragma unroll
        for (int i = 0; i < 8; i++) {
            int ch = tid + i * 128;
            int r = ch >> 4, c = ch & 15;
            uint32_t off = (uint32_t)(r * FSTR + c * 8) * 2;
            CP_ASYNC16(sb + 3 * FTB + off, vh + (size_t)r * HD + c * 8);
        }
        CP_COMMIT();

        CP_WAIT1();
        __syncthreads();

        float sc[8][4];
#pragma unroll
        for (int nt = 0; nt < 8; nt++)
#pragma unroll
            for (int e = 0; e < 4; e++) sc[nt][e] = 0.f;

#pragma unroll
        for (int kb = 0; kb < 8; kb++) {
            uint32_t qh4[4], ql4[4];
            uint32_t ko = kb * 32;
            LDSM_X4(qh4[0], qh4[1], qh4[2], qh4[3], sb + q_add + ko);
            LDSM_X4(ql4[0], ql4[1], ql4[2], ql4[3], sb + FTB + q_add + ko);
            uint32_t kh4[4][4];
#pragma unroll
            for (int pr = 0; pr < 4; pr++) {
                uint32_t ra = pr * 16 * FSTR * 2 + ko;
                LDSM_X4(kh4[pr][0], kh4[pr][1], kh4[pr][2], kh4[pr][3], sb + 2 * FTB + k_add + ra);
            }
#pragma unroll
            for (int nt = 0; nt < 8; nt++) {
                int pr = nt >> 1, ix = (nt & 1) * 2;
                MMA16816(sc[nt], qh4, kh4[pr][ix], kh4[pr][ix + 1]);
            }
#pragma unroll
            for (int nt = 0; nt < 8; nt++) {
                int pr = nt >> 1, ix = (nt & 1) * 2;
                MMA16816(sc[nt], ql4, kh4[pr][ix], kh4[pr][ix + 1]);
            }
        }

        if (j == ntile - 1) {
            int row0 = q0 + wm * 16 + (lane >> 2);
#pragma unroll
            for (int nt = 0; nt < 8; nt++) {
                int col = j * 64 + nt * 8 + (lane & 3) * 2;
#pragma unroll
                for (int e = 0; e < 4; e++) {
                    int cc = col + (e & 1);
                    int rr = row0 + ((e >> 1) << 3);
                    if (cc > rr) sc[nt][e] = -1e30f;
                }
            }
        }

#pragma unroll
        for (int half = 0; half < 2; half++) {
            int e0 = half * 2;
            float mx = -1e30f;
#pragma unroll
            for (int nt = 0; nt < 8; nt++)
                mx = fmaxf(mx, fmaxf(sc[nt][e0], sc[nt][e0 + 1]));
            mx = fmaxf(mx, __shfl_xor_sync(0xffffffff, mx, 1));
            mx = fmaxf(mx, __shfl_xor_sync(0xffffffff, mx, 2));
            float mnew = fmaxf(mrow[half], mx);
            float alpha = __expf(mrow[half] - mnew);
            float sum = 0.f;
#pragma unroll
            for (int nt = 0; nt < 8; nt++) {
                float p0 = __expf(sc[nt][e0]     - mnew);
                float p1 = __expf(sc[nt][e0 + 1] - mnew);
                sc[nt][e0] = p0; sc[nt][e0 + 1] = p1;
                sum += p0 + p1;
            }
            sum += __shfl_xor_sync(0xffffffff, sum, 1);
            sum += __shfl_xor_sync(0xffffffff, sum, 2);
            lrow[half] = lrow[half] * alpha + sum;
            mrow[half] = mnew;
#pragma unroll
            for (int nt = 0; nt < 16; nt++) {
                oc[nt][e0]     *= alpha;
                oc[nt][e0 + 1] *= alpha;
            }
        }

        CP_WAIT0();
        __syncthreads();

#pragma unroll
        for (int kb2 = 0; kb2 < 4; kb2++) {
            int nt0 = kb2 * 2, nt1 = nt0 + 1;
            uint32_t ph[4];
#pragma unroll
            for (int r4 = 0; r4 < 4; r4++) {
                int nts = (r4 >> 1) ? nt1 : nt0;
                int eb = (r4 & 1) * 2;
                ph[r4] = packh2(__float2half_rn(sc[nts][eb]),
                                __float2half_rn(sc[nts][eb + 1]));
            }
            uint32_t vrow = kb2 * 16 * FSTR * 2;
#pragma unroll
            for (int np = 0; np < 8; np++) {
                uint32_t va = sb + 3 * FTB + v_add + vrow + np * 32;
                uint32_t v4h[4];
                LDSM_X4T(v4h[0], v4h[1], v4h[2], v4h[3], va);
                int nt = np * 2;
                MMA16816(oc[nt],     ph, v4h[0], v4h[1]);
                MMA16816(oc[nt + 1], ph, v4h[2], v4h[3]);
            }
        }
    }

#pragma unroll
    for (int half = 0; half < 2; half++) {
        float inv_l = 1.0f / lrow[half];
        int row = q0 + wm * 16 + (lane >> 2) + half * 8;
        size_t ob = (((size_t)b * Tt + row) * Hh + h) * HD;
#pragma unroll
        for (int nt = 0; nt < 16; nt++) {
            int d = nt * 8 + (lane & 3) * 2;
            float v0 = oc[nt][half * 2] * inv_l;
            float v1 = oc[nt][half * 2 + 1] * inv_l;
            *(__half2*)&Oh[ob + d] = __halves2half2(__float2half_rn(v0),
                                                    __float2half_rn(v1));
        }
    }
}

// ---------------- launch ----------------
extern "C" void kernel_launch(void* const* d_in, const int* in_sizes, int n_in,
                              void* d_out, int out_size)
{
    const float* x  = (const float*)d_in[0];
    const float* Wq = (const float*)d_in[1];
    const float* Wk = (const float*)d_in[2];
    const float* Wv = (const float*)d_in[3];
    const float* Wo = (const float*)d_in[4];
    float* out = (float*)d_out;

    __half *xsh, *osh, *wqkvh, *woh;
    __half *qh, *ql, *kh, *vh;
    float2* rope;
    cudaGetSymbolAddress((void**)&xsh, g_xs_h);
    cudaGetSymbolAddress((void**)&osh, g_os_h);
    cudaGetSymbolAddress((void**)&wqkvh, g_wqkvt_h);
    cudaGetSymbolAddress((void**)&woh, g_wot_h);
    cudaGetSymbolAddress((void**)&qh, g_qh);
    cudaGetSymbolAddress((void**)&ql, g_ql);
    cudaGetSymbolAddress((void**)&kh, g_kh);
    cudaGetSymbolAddress((void**)&vh, g_vh);
    cudaGetSymbolAddress((void**)&rope, g_rope);

    const int M = Bsz * Tt;   // 4096
    const int n4 = M * Dd / 4;

    cudaFuncSetAttribute(mma_gemm, cudaFuncAttributeMaxDynamicSharedMemorySize, GEMM_SMEM);
    cudaFuncSetAttribute(flash_mma, cudaFuncAttributeMaxDynamicSharedMemorySize, FLASH_SMEM);

    tsplit_all_kernel<<<dim3(64, 64, 4), dim3(32, 8)>>>(Wq, Wk, Wv, Wo, wqkvh, woh);
    convert_kernel<<<4096, 256>>>(x, xsh, n4);
    rope_table_kernel<<<(Tt * 64) / 256, 256>>>(rope);

    // fused QKV projection + RoPE + permute (x 1-term now)
    mma_gemm<<<dim3(NQKV / 128, M / 128), 256, GEMM_SMEM>>>(
        xsh, xsh, wqkvh, nullptr, M, NQKV, Dd, 1, 0,
        rope, qh, ql, kh, vh);
    // flash attention
    flash_mma<<<dim3(Tt / 64, Hh, Bsz), 128, FLASH_SMEM>>>(qh, ql, kh, vh, osh);
    // output projection -> d_out (O 1-term)
    mma_gemm<<<dim3(Dd / 128, M / 128), 256, GEMM_SMEM>>>(
        osh, osh, woh, out, M, Dd, Dd, 0, 0,
        rope, qh, ql, kh, vh);
}